// round 16
// baseline (speedup 1.0000x reference)
#include <cuda_runtime.h>
#include <cuda_bf16.h>
#include <math.h>
#include <stdint.h>

// Problem constants
#define BB   2
#define TT   2048
#define CCH  2048
#define HH   16
#define HKK  4
#define DD   128
#define MR   (BB*TT)          // 4096 rows
#define KGEMM 2048            // K of every GEMM here

// Weight scratch offsets (bf16 transposed [N][K]); k,v,dk,dv contiguous
#define WQ_OFF  0u
#define WK_OFF  4194304u
#define WP_OFF  8388608u
#define WTOT    12582912u

// ---------------------------------------------------------------------------
// Scratch (device globals; no allocation allowed)
// ---------------------------------------------------------------------------
__device__ __nv_bfloat16 g_qh[(size_t)MR*CCH],   g_ql[(size_t)MR*CCH];    // q hi/lo (B,T,H*D)
__device__ __nv_bfloat16 g_kh[(size_t)MR*512],   g_kl[(size_t)MR*512];    // k hi/lo (B,T,HK*D)
__device__ __nv_bfloat16 g_vh[(size_t)MR*512],   g_vl[(size_t)MR*512];    // v hi/lo
__device__ __nv_bfloat16 g_xh[(size_t)MR*CCH],   g_xl[(size_t)MR*CCH];
__device__ __nv_bfloat16 g_yh[(size_t)MR*CCH],   g_yl[(size_t)MR*CCH];
__device__ __nv_bfloat16 g_wh[WTOT], g_wl[WTOT];

// ---------------------------------------------------------------------------
// mma.sync m16n8k16 bf16 + helpers
// ---------------------------------------------------------------------------
__device__ __forceinline__ void mma16816(float* c, const uint32_t* a, const uint32_t* b)
{
    asm volatile(
        "mma.sync.aligned.m16n8k16.row.col.f32.bf16.bf16.f32 "
        "{%0,%1,%2,%3}, {%4,%5,%6,%7}, {%8,%9}, {%0,%1,%2,%3};\n"
        : "+f"(c[0]), "+f"(c[1]), "+f"(c[2]), "+f"(c[3])
        : "r"(a[0]), "r"(a[1]), "r"(a[2]), "r"(a[3]), "r"(b[0]), "r"(b[1]));
}

__device__ __forceinline__ void ldsm4(uint32_t* d, uint32_t addr)
{
    asm volatile("ldmatrix.sync.aligned.m8n8.x4.shared.b16 {%0,%1,%2,%3}, [%4];"
        : "=r"(d[0]), "=r"(d[1]), "=r"(d[2]), "=r"(d[3]) : "r"(addr));
}

__device__ __forceinline__ uint32_t pack_hi2(float a, float b)
{
    __nv_bfloat162 h = __floats2bfloat162_rn(a, b);
    return *reinterpret_cast<uint32_t*>(&h);
}
__device__ __forceinline__ uint32_t pack_lo2(float a, float b, uint32_t hi)
{
    __nv_bfloat162 h = *reinterpret_cast<__nv_bfloat162*>(&hi);
    __nv_bfloat162 l = __floats2bfloat162_rn(a - __bfloat162float(h.x),
                                             b - __bfloat162float(h.y));
    return *reinterpret_cast<uint32_t*>(&l);
}
__device__ __forceinline__ uint32_t smem_u32(const void* p)
{
    uint32_t a;
    asm("{ .reg .u64 t; cvta.to.shared.u64 t, %1; cvt.u32.u64 %0, t; }"
        : "=r"(a) : "l"(p));
    return a;
}
__device__ __forceinline__ void cpa16(uint32_t s, const void* g)
{
    asm volatile("cp.async.cg.shared.global [%0], [%1], 16;" :: "r"(s), "l"(g));
}
#define CP_COMMIT asm volatile("cp.async.commit_group;" ::: "memory")
#define CP_WAIT1  asm volatile("cp.async.wait_group 1;" ::: "memory")
#define CP_WAIT0  asm volatile("cp.async.wait_group 0;" ::: "memory")

// ---------------------------------------------------------------------------
// Split fp32 -> bf16 hi/lo (elementwise, vectorized)
// ---------------------------------------------------------------------------
__global__ __launch_bounds__(256)
void split_f32(const float* __restrict__ s, __nv_bfloat16* __restrict__ dh,
               __nv_bfloat16* __restrict__ dl, int n4)
{
    int i = blockIdx.x * blockDim.x + threadIdx.x;
    if (i >= n4) return;
    float4 v = reinterpret_cast<const float4*>(s)[i];
    uint32_t h0 = pack_hi2(v.x, v.y), h1 = pack_hi2(v.z, v.w);
    uint32_t l0 = pack_lo2(v.x, v.y, h0), l1 = pack_lo2(v.z, v.w, h1);
    reinterpret_cast<uint2*>(dh)[i] = make_uint2(h0, h1);
    reinterpret_cast<uint2*>(dl)[i] = make_uint2(l0, l1);
}

// ---------------------------------------------------------------------------
// Transpose W[K][N] fp32 -> Wt[N][K] bf16 hi/lo. Block (32,8), grid (N/32,K/32).
// ---------------------------------------------------------------------------
__global__ __launch_bounds__(256)
void transpose_w(const float* __restrict__ W, __nv_bfloat16* __restrict__ Th,
                 __nv_bfloat16* __restrict__ Tl, int K, int N)
{
    __shared__ float tile[32][33];
    const int n0 = blockIdx.x * 32, k0 = blockIdx.y * 32;
    const int tx = threadIdx.x, ty = threadIdx.y;
    #pragma unroll
    for (int i = 0; i < 4; i++)
        tile[ty + i * 8][tx] = W[(size_t)(k0 + ty + i * 8) * N + n0 + tx];
    __syncthreads();
    #pragma unroll
    for (int i = 0; i < 4; i++) {
        int n = ty + i * 8;
        float v = tile[tx][n];
        __nv_bfloat16 h = __float2bfloat16(v);
        __nv_bfloat16 l = __float2bfloat16(v - __bfloat162float(h));
        size_t off = (size_t)(n0 + n) * K + k0 + tx;
        Th[off] = h;
        Tl[off] = l;
    }
}

// ---------------------------------------------------------------------------
// Merged transpose for the 4 x 512-wide weights (k,v,dk,dv) -> one [2048][K].
// ---------------------------------------------------------------------------
__global__ __launch_bounds__(256)
void transpose_kvdd(const float* __restrict__ Wk, const float* __restrict__ Wv,
                    const float* __restrict__ Wdk, const float* __restrict__ Wdv,
                    __nv_bfloat16* __restrict__ Th, __nv_bfloat16* __restrict__ Tl)
{
    __shared__ float tile[32][33];
    const int sel = blockIdx.x >> 4;
    const float* W = (sel == 0) ? Wk : (sel == 1) ? Wv : (sel == 2) ? Wdk : Wdv;
    const int n0l = (blockIdx.x & 15) * 32;
    const int gn0 = blockIdx.x * 32;
    const int k0 = blockIdx.y * 32;
    const int tx = threadIdx.x, ty = threadIdx.y;
    #pragma unroll
    for (int i = 0; i < 4; i++)
        tile[ty + i * 8][tx] = W[(size_t)(k0 + ty + i * 8) * 512 + n0l + tx];
    __syncthreads();
    #pragma unroll
    for (int i = 0; i < 4; i++) {
        int n = ty + i * 8;
        float v = tile[tx][n];
        __nv_bfloat16 h = __float2bfloat16(v);
        __nv_bfloat16 l = __float2bfloat16(v - __bfloat162float(h));
        size_t off = (size_t)(gn0 + n) * KGEMM + k0 + tx;
        Th[off] = h;
        Tl[off] = l;
    }
}

// ---------------------------------------------------------------------------
// HMMA GEMM, 2-stage cp.async pipeline + ldmatrix fragment loads.
// MODE 0: plain fp32 -> C0. MODE 1: RoPE -> bf16 hi/lo D0h/D0l (stride 2048).
// MODE 3 (N=2048): sub0: RoPE -> D0h/D0l (stride 512, k). sub1: plain ->
//   D1h/D1l (stride 512, v). sub2/3: (B,HK,T,D) fp32 -> C0 / C1.
// ---------------------------------------------------------------------------
#define SA 40
#define GSTG 40960
#define GEMM_DYN (2 * GSTG)

template<int MODE>
__global__ __launch_bounds__(256, 2)
void gemm_mma(const __nv_bfloat16* __restrict__ AH, const __nv_bfloat16* __restrict__ AL,
              const __nv_bfloat16* __restrict__ BH, const __nv_bfloat16* __restrict__ BL,
              float* __restrict__ C0, float* __restrict__ C1,
              __nv_bfloat16* __restrict__ D0h, __nv_bfloat16* __restrict__ D0l,
              __nv_bfloat16* __restrict__ D1h, __nv_bfloat16* __restrict__ D1l,
              int N, const float* __restrict__ cosT, const float* __restrict__ sinT)
{
    extern __shared__ char gsm[];
    const uint32_t sb = smem_u32(gsm);
    const int tid = threadIdx.x;
    const int wid = tid >> 5, lane = tid & 31;
    const int g = lane >> 2, tig = lane & 3;
    const int wm = wid >> 2, wn = wid & 3;
    const int m0 = blockIdx.y * 128;
    const int n0 = blockIdx.x * 128;

    float acc[4][4][4];
    #pragma unroll
    for (int mt = 0; mt < 4; mt++)
        #pragma unroll
        for (int nt = 0; nt < 4; nt++)
            #pragma unroll
            for (int e = 0; e < 4; e++) acc[mt][nt][e] = 0.f;

    const int row = tid >> 2, part = tid & 3;
    const uint32_t so = (uint32_t)(row * SA + part * 8) * 2;

    const int r8 = lane & 7;
    const int ahf = (lane >> 3) & 1, ak8 = (lane >> 4) & 1;
    uint32_t aoff[4];
    #pragma unroll
    for (int mt = 0; mt < 4; mt++)
        aoff[mt] = (uint32_t)(((wm * 64 + mt * 16 + ahf * 8 + r8) * SA + ak8 * 8) * 2);
    const int bk8 = (lane >> 3) & 1, ntp = (lane >> 4) & 1;
    uint32_t boff[2];
    #pragma unroll
    for (int np = 0; np < 2; np++)
        boff[np] = (uint32_t)(((wn * 32 + (np * 2 + ntp) * 8 + r8) * SA + bk8 * 8) * 2);

    auto issue_load = [&](int stage, int kc) {
        const int k0 = kc * 32;
        const uint32_t st = sb + stage * GSTG;
        #pragma unroll
        for (int it = 0; it < 2; it++) {
            int r2 = row + it * 64;
            size_t ga = (size_t)(m0 + r2) * KGEMM + k0 + part * 8;
            size_t gb = (size_t)(n0 + r2) * KGEMM + k0 + part * 8;
            uint32_t s2 = so + (uint32_t)(it * 64 * SA * 2);
            cpa16(st + s2,         AH + ga);
            cpa16(st + 10240 + s2, AL + ga);
            cpa16(st + 20480 + s2, BH + gb);
            cpa16(st + 30720 + s2, BL + gb);
        }
        CP_COMMIT;
    };

    const int nk = KGEMM / 32;   // 64
    issue_load(0, 0);

    for (int kc = 0; kc < nk; kc++) {
        const int st = kc & 1;
        if (kc + 1 < nk) { issue_load((kc + 1) & 1, kc + 1); CP_WAIT1; }
        else             { CP_WAIT0; }
        __syncthreads();

        const uint32_t stb = sb + st * GSTG;
        #pragma unroll
        for (int ks = 0; ks < 2; ks++) {
            const uint32_t ko = (uint32_t)(ks * 32);
            uint32_t bh2[2][4], bl2[2][4];
            ldsm4(bh2[0], stb + 20480 + boff[0] + ko);
            ldsm4(bh2[1], stb + 20480 + boff[1] + ko);
            ldsm4(bl2[0], stb + 30720 + boff[0] + ko);
            ldsm4(bl2[1], stb + 30720 + boff[1] + ko);

            uint32_t af[4][4];
            #pragma unroll
            for (int mt = 0; mt < 4; mt++)
                ldsm4(af[mt], stb + aoff[mt] + ko);
            #pragma unroll
            for (int mt = 0; mt < 4; mt++)
                #pragma unroll
                for (int nt = 0; nt < 4; nt++) {
                    mma16816(acc[mt][nt], af[mt], &bh2[nt >> 1][(nt & 1) * 2]);
                    mma16816(acc[mt][nt], af[mt], &bl2[nt >> 1][(nt & 1) * 2]);
                }
            #pragma unroll
            for (int mt = 0; mt < 4; mt++)
                ldsm4(af[mt], stb + 10240 + aoff[mt] + ko);
            #pragma unroll
            for (int mt = 0; mt < 4; mt++)
                #pragma unroll
                for (int nt = 0; nt < 4; nt++)
                    mma16816(acc[mt][nt], af[mt], &bh2[nt >> 1][(nt & 1) * 2]);
        }
        __syncthreads();
    }

    const int sub = n0 >> 9;
    #pragma unroll
    for (int mt = 0; mt < 4; mt++) {
        const int r0 = m0 + wm * 64 + mt * 16 + g;
        #pragma unroll
        for (int nt = 0; nt < 4; nt++) {
            const int n = n0 + wn * 32 + nt * 8 + 2 * tig;
            #pragma unroll
            for (int half = 0; half < 2; half++) {
                const int m = r0 + half * 8;
                float e = acc[mt][nt][half * 2 + 0];
                float o = acc[mt][nt][half * 2 + 1];
                const bool dorope = (MODE == 1) || (MODE == 3 && sub == 0);
                if (dorope) {
                    int t = m & (TT - 1);
                    int j0 = (n & (DD - 1)) >> 1;
                    float cc = cosT[(size_t)t * (DD / 2) + j0];
                    float ss = sinT[(size_t)t * (DD / 2) + j0];
                    float e2 = e * cc - o * ss;
                    o = e * ss + o * cc;
                    e = e2;
                }
                if (MODE == 1) {
                    uint32_t h = pack_hi2(e, o), l = pack_lo2(e, o, h);
                    size_t off = (size_t)m * CCH + n;
                    *reinterpret_cast<uint32_t*>(&D0h[off]) = h;
                    *reinterpret_cast<uint32_t*>(&D0l[off]) = l;
                } else if (MODE == 3) {
                    int nn = n & 511;
                    if (sub == 0) {
                        uint32_t h = pack_hi2(e, o), l = pack_lo2(e, o, h);
                        size_t off = (size_t)m * 512 + nn;
                        *reinterpret_cast<uint32_t*>(&D0h[off]) = h;
                        *reinterpret_cast<uint32_t*>(&D0l[off]) = l;
                    } else if (sub == 1) {
                        uint32_t h = pack_hi2(e, o), l = pack_lo2(e, o, h);
                        size_t off = (size_t)m * 512 + nn;
                        *reinterpret_cast<uint32_t*>(&D1h[off]) = h;
                        *reinterpret_cast<uint32_t*>(&D1l[off]) = l;
                    } else {
                        int b = m >> 11, t = m & (TT - 1);
                        int hk = nn >> 7, d = n & (DD - 1);
                        float* dst = (sub == 2) ? C0 : C1;
                        *reinterpret_cast<float2*>(
                            &dst[(((size_t)(b * HKK + hk) * TT + t) * DD) + d]) =
                            make_float2(e, o);
                    }
                } else {
                    *reinterpret_cast<float2*>(&C0[(size_t)m * N + n]) =
                        make_float2(e, o);
                }
            }
        }
    }
}

// ---------------------------------------------------------------------------
// HMMA flash attention, bf16x3; q/k/v pre-split bf16 hi/lo inputs.
// Longest-first CTA order (it reversed). Same mma set as 1530us kernel.
// ---------------------------------------------------------------------------
#define QS 136
#define VS 72
#define ATT_SMEM ((2*128*QS + 2*64*QS + 2*128*VS) * 2)

__global__ __launch_bounds__(256, 1)
void attn_mma(const __nv_bfloat16* __restrict__ qh, const __nv_bfloat16* __restrict__ ql,
              const __nv_bfloat16* __restrict__ kh, const __nv_bfloat16* __restrict__ kl,
              const __nv_bfloat16* __restrict__ vh, const __nv_bfloat16* __restrict__ vl,
              __nv_bfloat16* __restrict__ yh, __nv_bfloat16* __restrict__ yl)
{
    extern __shared__ __nv_bfloat16 smp[];
    __nv_bfloat16* Qh  = smp;
    __nv_bfloat16* Ql  = Qh + 128 * QS;
    __nv_bfloat16* Kh  = Ql + 128 * QS;
    __nv_bfloat16* Kl  = Kh + 64 * QS;
    __nv_bfloat16* VTh = Kl + 64 * QS;
    __nv_bfloat16* VTl = VTh + 128 * VS;

    const int it = (int)gridDim.x - 1 - (int)blockIdx.x;   // longest tiles first
    const int h  = blockIdx.y;
    const int b  = blockIdx.z;
    const int gk = h >> 2;
    const int t0 = it * 128;
    const int tid = threadIdx.x;
    const int wm = tid >> 5, lane = tid & 31;
    const int g = lane >> 2, tig = lane & 3;
    const float scale = 0.08838834764831845f;

    // Q tile copy (pre-split): 128 rows x 128 bf16, uint4 chunks
    for (int e = tid; e < 128 * 16; e += 256) {
        int row = e >> 4, c8 = (e & 15) << 3;
        size_t gq = (size_t)(b * TT + t0 + row) * CCH + h * DD + c8;
        *reinterpret_cast<uint4*>(&Qh[row * QS + c8]) =
            *reinterpret_cast<const uint4*>(&qh[gq]);
        *reinterpret_cast<uint4*>(&Ql[row * QS + c8]) =
            *reinterpret_cast<const uint4*>(&ql[gq]);
    }

    float o[16][4];
    #pragma unroll
    for (int dt = 0; dt < 16; dt++)
        #pragma unroll
        for (int e = 0; e < 4; e++) o[dt][e] = 0.f;
    float m0r = -INFINITY, m1r = -INFINITY, l0r = 0.f, l1r = 0.f;

    const int njt = 2 * it + 2;
    for (int jt = 0; jt < njt; jt++) {
        const int s0 = jt * 64;
        __syncthreads();

        // K tile copy
        for (int e = tid; e < 64 * 16; e += 256) {
            int row = e >> 4, c8 = (e & 15) << 3;
            size_t gkk = (size_t)(b * TT + s0 + row) * 512 + gk * DD + c8;
            *reinterpret_cast<uint4*>(&Kh[row * QS + c8]) =
                *reinterpret_cast<const uint4*>(&kh[gkk]);
            *reinterpret_cast<uint4*>(&Kl[row * QS + c8]) =
                *reinterpret_cast<const uint4*>(&kl[gkk]);
        }
        // V tile transposed: VT[d][s]
        {
            const int d = tid & 127, sb2 = (tid >> 7) * 32;
            const unsigned short* vbh = reinterpret_cast<const unsigned short*>(
                &vh[(size_t)(b * TT + s0 + sb2) * 512 + gk * DD + d]);
            const unsigned short* vbl = reinterpret_cast<const unsigned short*>(
                &vl[(size_t)(b * TT + s0 + sb2) * 512 + gk * DD + d]);
            #pragma unroll
            for (int i = 0; i < 8; i++) {
                uint32_t a0 = vbh[(size_t)(i * 4 + 0) * 512];
                uint32_t a1 = vbh[(size_t)(i * 4 + 1) * 512];
                uint32_t a2 = vbh[(size_t)(i * 4 + 2) * 512];
                uint32_t a3 = vbh[(size_t)(i * 4 + 3) * 512];
                uint32_t c0 = vbl[(size_t)(i * 4 + 0) * 512];
                uint32_t c1 = vbl[(size_t)(i * 4 + 1) * 512];
                uint32_t c2 = vbl[(size_t)(i * 4 + 2) * 512];
                uint32_t c3 = vbl[(size_t)(i * 4 + 3) * 512];
                int so = d * VS + sb2 + i * 4;
                *reinterpret_cast<uint2*>(&VTh[so]) =
                    make_uint2(a0 | (a1 << 16), a2 | (a3 << 16));
                *reinterpret_cast<uint2*>(&VTl[so]) =
                    make_uint2(c0 | (c1 << 16), c2 | (c3 << 16));
            }
        }
        __syncthreads();

        float sc[8][4];
        #pragma unroll
        for (int nt = 0; nt < 8; nt++)
            #pragma unroll
            for (int e = 0; e < 4; e++) sc[nt][e] = 0.f;

        #pragma unroll
        for (int kk = 0; kk < 8; kk++) {
            const int kcol = kk * 16 + 2 * tig;
            const int ar = (wm * 16 + g) * QS;
            uint32_t ah[4], al[4];
            ah[0] = *reinterpret_cast<const uint32_t*>(&Qh[ar + kcol]);
            ah[1] = *reinterpret_cast<const uint32_t*>(&Qh[ar + 8 * QS + kcol]);
            ah[2] = *reinterpret_cast<const uint32_t*>(&Qh[ar + kcol + 8]);
            ah[3] = *reinterpret_cast<const uint32_t*>(&Qh[ar + 8 * QS + kcol + 8]);
            al[0] = *reinterpret_cast<const uint32_t*>(&Ql[ar + kcol]);
            al[1] = *reinterpret_cast<const uint32_t*>(&Ql[ar + 8 * QS + kcol]);
            al[2] = *reinterpret_cast<const uint32_t*>(&Ql[ar + kcol + 8]);
            al[3] = *reinterpret_cast<const uint32_t*>(&Ql[ar + 8 * QS + kcol + 8]);
            #pragma unroll
            for (int nt = 0; nt < 8; nt++) {
                const int br = (nt * 8 + g) * QS;
                uint32_t bh[2], bl[2];
                bh[0] = *reinterpret_cast<const uint32_t*>(&Kh[br + kcol]);
                bh[1] = *reinterpret_cast<const uint32_t*>(&Kh[br + kcol + 8]);
                bl[0] = *reinterpret_cast<const uint32_t*>(&Kl[br + kcol]);
                bl[1] = *reinterpret_cast<const uint32_t*>(&Kl[br + kcol + 8]);
                mma16816(sc[nt], ah, bh);
                mma16816(sc[nt], ah, bl);
                mma16816(sc[nt], al, bh);
            }
        }

        const int row0 = t0 + wm * 16 + g;
        const bool needmask = (s0 + 63 > row0);
        float mx0 = -INFINITY, mx1 = -INFINITY;
        #pragma unroll
        for (int nt = 0; nt < 8; nt++) {
            #pragma unroll
            for (int e = 0; e < 4; e++) sc[nt][e] *= scale;
            if (needmask) {
                int c0 = s0 + nt * 8 + 2 * tig;
                if (c0     > row0)     sc[nt][0] = -INFINITY;
                if (c0 + 1 > row0)     sc[nt][1] = -INFINITY;
                if (c0     > row0 + 8) sc[nt][2] = -INFINITY;
                if (c0 + 1 > row0 + 8) sc[nt][3] = -INFINITY;
            }
            mx0 = fmaxf(mx0, fmaxf(sc[nt][0], sc[nt][1]));
            mx1 = fmaxf(mx1, fmaxf(sc[nt][2], sc[nt][3]));
        }
        #pragma unroll
        for (int msk = 1; msk < 4; msk <<= 1) {
            mx0 = fmaxf(mx0, __shfl_xor_sync(0xffffffffu, mx0, msk));
            mx1 = fmaxf(mx1, __shfl_xor_sync(0xffffffffu, mx1, msk));
        }
        float mn0 = fmaxf(m0r, mx0), mn1 = fmaxf(m1r, mx1);
        float f0 = __expf(m0r - mn0), f1 = __expf(m1r - mn1);
        float s0s = 0.f, s1s = 0.f;
        #pragma unroll
        for (int nt = 0; nt < 8; nt++) {
            float p0 = __expf(sc[nt][0] - mn0); sc[nt][0] = p0; s0s += p0;
            float p1 = __expf(sc[nt][1] - mn0); sc[nt][1] = p1; s0s += p1;
            float p2 = __expf(sc[nt][2] - mn1); sc[nt][2] = p2; s1s += p2;
            float p3 = __expf(sc[nt][3] - mn1); sc[nt][3] = p3; s1s += p3;
        }
        #pragma unroll
        for (int msk = 1; msk < 4; msk <<= 1) {
            s0s += __shfl_xor_sync(0xffffffffu, s0s, msk);
            s1s += __shfl_xor_sync(0xffffffffu, s1s, msk);
        }
        l0r = l0r * f0 + s0s; l1r = l1r * f1 + s1s;
        m0r = mn0; m1r = mn1;
        #pragma unroll
        for (int dt = 0; dt < 16; dt++) {
            o[dt][0] *= f0; o[dt][1] *= f0;
            o[dt][2] *= f1; o[dt][3] *= f1;
        }

        #pragma unroll
        for (int kks = 0; kks < 4; kks++) {
            uint32_t pha[4], pla[4];
            pha[0] = pack_hi2(sc[2*kks][0],   sc[2*kks][1]);
            pla[0] = pack_lo2(sc[2*kks][0],   sc[2*kks][1],   pha[0]);
            pha[1] = pack_hi2(sc[2*kks][2],   sc[2*kks][3]);
            pla[1] = pack_lo2(sc[2*kks][2],   sc[2*kks][3],   pha[1]);
            pha[2] = pack_hi2(sc[2*kks+1][0], sc[2*kks+1][1]);
            pla[2] = pack_lo2(sc[2*kks+1][0], sc[2*kks+1][1], pha[2]);
            pha[3] = pack_hi2(sc[2*kks+1][2], sc[2*kks+1][3]);
            pla[3] = pack_lo2(sc[2*kks+1][2], sc[2*kks+1][3], pha[3]);
            #pragma unroll
            for (int dt = 0; dt < 16; dt++) {
                const int br = (dt * 8 + g) * VS + kks * 16 + 2 * tig;
                uint32_t bh[2], bl[2];
                bh[0] = *reinterpret_cast<const uint32_t*>(&VTh[br]);
                bh[1] = *reinterpret_cast<const uint32_t*>(&VTh[br + 8]);
                bl[0] = *reinterpret_cast<const uint32_t*>(&VTl[br]);
                bl[1] = *reinterpret_cast<const uint32_t*>(&VTl[br + 8]);
                mma16816(o[dt], pha, bh);
                mma16816(o[dt], pha, bl);
                mma16816(o[dt], pla, bh);
            }
        }
    }

    const float inv0 = 1.f / l0r, inv1 = 1.f / l1r;
    const int row0 = t0 + wm * 16 + g;
    #pragma unroll
    for (int dt = 0; dt < 16; dt++) {
        int d = dt * 8 + 2 * tig;
        size_t b0 = ((size_t)(b * TT + row0) * HH + h) * DD + d;
        size_t b1 = ((size_t)(b * TT + row0 + 8) * HH + h) * DD + d;
        uint32_t h0 = pack_hi2(o[dt][0] * inv0, o[dt][1] * inv0);
        uint32_t l0 = pack_lo2(o[dt][0] * inv0, o[dt][1] * inv0, h0);
        uint32_t h1 = pack_hi2(o[dt][2] * inv1, o[dt][3] * inv1);
        uint32_t l1 = pack_lo2(o[dt][2] * inv1, o[dt][3] * inv1, h1);
        *reinterpret_cast<uint32_t*>(&yh[b0]) = h0;
        *reinterpret_cast<uint32_t*>(&yl[b0]) = l0;
        *reinterpret_cast<uint32_t*>(&yh[b1]) = h1;
        *reinterpret_cast<uint32_t*>(&yl[b1]) = l1;
    }
}

// ---------------------------------------------------------------------------
// Launch (single stream)
// ---------------------------------------------------------------------------
extern "C" void kernel_launch(void* const* d_in, const int* in_sizes, int n_in,
                              void* d_out, int out_size)
{
    const float* x      = (const float*)d_in[0];
    const float* w_q    = (const float*)d_in[1];
    const float* w_k    = (const float*)d_in[2];
    const float* w_v    = (const float*)d_in[3];
    const float* w_proj = (const float*)d_in[4];
    const float* w_dk   = (const float*)d_in[5];
    const float* w_dv   = (const float*)d_in[6];
    const float* fcos   = (const float*)d_in[7];
    const float* fsin   = (const float*)d_in[8];

    float* out    = (float*)d_out;
    float* out_y  = out;
    float* out_kw = out + (size_t)BB * TT * CCH;
    float* out_vw = out_kw + (size_t)BB * HKK * TT * DD;

    static __nv_bfloat16 *qh, *ql, *kh, *kl, *vh, *vl;
    static __nv_bfloat16 *xh, *xl, *yh, *yl, *wh, *wl;
    static bool init = false;
    if (!init) {
        init = true;
        cudaGetSymbolAddress((void**)&qh, g_qh);
        cudaGetSymbolAddress((void**)&ql, g_ql);
        cudaGetSymbolAddress((void**)&kh, g_kh);
        cudaGetSymbolAddress((void**)&kl, g_kl);
        cudaGetSymbolAddress((void**)&vh, g_vh);
        cudaGetSymbolAddress((void**)&vl, g_vl);
        cudaGetSymbolAddress((void**)&xh, g_xh);
        cudaGetSymbolAddress((void**)&xl, g_xl);
        cudaGetSymbolAddress((void**)&yh, g_yh);
        cudaGetSymbolAddress((void**)&yl, g_yl);
        cudaGetSymbolAddress((void**)&wh, g_wh);
        cudaGetSymbolAddress((void**)&wl, g_wl);
        cudaFuncSetAttribute(attn_mma,
                             cudaFuncAttributeMaxDynamicSharedMemorySize, ATT_SMEM);
        cudaFuncSetAttribute(gemm_mma<0>,
                             cudaFuncAttributeMaxDynamicSharedMemorySize, GEMM_DYN);
        cudaFuncSetAttribute(gemm_mma<1>,
                             cudaFuncAttributeMaxDynamicSharedMemorySize, GEMM_DYN);
        cudaFuncSetAttribute(gemm_mma<3>,
                             cudaFuncAttributeMaxDynamicSharedMemorySize, GEMM_DYN);
    }

    dim3 tb(32, 8);
    dim3 blk(256);
    const int MT = MR / 128;

    // 1) prep
    split_f32<<<(MR * CCH / 4 + 255) / 256, 256>>>(x, xh, xl, MR * CCH / 4);
    transpose_w<<<dim3(CCH / 32, CCH / 32), tb>>>(w_q, wh + WQ_OFF, wl + WQ_OFF, CCH, CCH);
    transpose_kvdd<<<dim3(64, CCH / 32), tb>>>(w_k, w_v, w_dk, w_dv, wh + WK_OFF, wl + WK_OFF);
    transpose_w<<<dim3(CCH / 32, CCH / 32), tb>>>(w_proj, wh + WP_OFF, wl + WP_OFF, CCH, CCH);

    // 2) projections (q -> bf16 pair; kvdd -> k/v bf16 pairs + dk/dv fp32 out)
    gemm_mma<1><<<dim3(16, MT), blk, GEMM_DYN>>>(xh, xl, wh + WQ_OFF, wl + WQ_OFF,
                                                 0, 0, qh, ql, 0, 0, CCH, fcos, fsin);
    gemm_mma<3><<<dim3(16, MT), blk, GEMM_DYN>>>(xh, xl, wh + WK_OFF, wl + WK_OFF,
                                                 out_kw, out_vw, kh, kl, vh, vl,
                                                 2048, fcos, fsin);
    // 3) attention
    attn_mma<<<dim3(TT / 128, HH, BB), blk, ATT_SMEM>>>(qh, ql, kh, kl, vh, vl, yh, yl);
    // 4) output projection
    gemm_mma<0><<<dim3(16, MT), blk, GEMM_DYN>>>(yh, yl, wh + WP_OFF, wl + WP_OFF,
                                                 out_y, 0, 0, 0, 0, 0, CCH, 0, 0);
}